// round 4
// baseline (speedup 1.0000x reference)
#include <cuda_runtime.h>
#include <math.h>

#define NB 4
#define C 256
#define P 2304          // 48*48
#define SIGMA 0.1f
#define INV_SIGMA 10.0f // B_CONST / SIGMA with B_CONST = 1
#define EPS 1e-5f

// ---------------- scratch (static device globals; no runtime alloc) ----------
__device__ float g_mean[C];
__device__ float g_invT[NB * P];
__device__ float g_invI[NB * P];
__device__ float g_fTn[NB * P * C];   // [n][p][c] centered+normalized T
__device__ float g_fIn[NB * P * C];   // [n][p][c] centered+normalized I
__device__ float g_D[NB * P * P];     // raw_dist [n][p][j]  (~85 MB)
__device__ int   g_colMin[NB * P];    // float bits, min over p per column j
__device__ float g_colSum[NB * P];    // sum_p exp(...)
__device__ float g_bArr[NB * P];      // 10/(min+eps)
__device__ float g_cArr[NB * P];      // 10 - log(colSum)
__device__ float g_sampSum[NB];

// ---------------- 1) per-channel mean of featureT over (N,H,W) ---------------
__global__ void k_mean(const float* __restrict__ fT) {
    int c = blockIdx.x;
    float s = 0.f;
    for (int i = threadIdx.x; i < NB * P; i += blockDim.x) {
        int n = i / P, p = i - n * P;
        s += fT[(n * C + c) * P + p];
    }
    __shared__ float red[256];
    red[threadIdx.x] = s;
    __syncthreads();
    for (int o = 128; o > 0; o >>= 1) {
        if (threadIdx.x < o) red[threadIdx.x] += red[threadIdx.x + o];
        __syncthreads();
    }
    if (threadIdx.x == 0) g_mean[c] = red[0] * (1.0f / (NB * P));
}

// ---------------- 2) per-position inverse L2 norm (centered) ------------------
__global__ void k_inv(const float* __restrict__ fT, const float* __restrict__ fI) {
    __shared__ float sm[C];
    for (int i = threadIdx.x; i < C; i += blockDim.x) sm[i] = g_mean[i];
    __syncthreads();
    int pos = blockIdx.x * blockDim.x + threadIdx.x;   // 0..NB*P-1
    int n = pos / P, p = pos - n * P;
    const float* bT = fT + (n * C) * P + p;
    const float* bI = fI + (n * C) * P + p;
    float sT = 0.f, sI = 0.f;
#pragma unroll 8
    for (int c = 0; c < C; c++) {
        float m  = sm[c];
        float xT = bT[c * P] - m;
        float xI = bI[c * P] - m;
        sT += xT * xT;
        sI += xI * xI;
    }
    g_invT[pos] = 1.0f / sqrtf(sT);
    g_invI[pos] = 1.0f / sqrtf(sI);
}

// ---------------- 3) center + normalize + transpose to [n][p][c] -------------
__global__ void k_norm_transpose(const float* __restrict__ fT, const float* __restrict__ fI) {
    __shared__ float tile[32][33];
    int p0 = blockIdx.x * 32;
    int c0 = blockIdx.y * 32;
    int n  = blockIdx.z;
    int tx = threadIdx.x, ty = threadIdx.y;

#pragma unroll
    for (int sel = 0; sel < 2; sel++) {
        const float* src = sel ? fI : fT;
        float*       dst = sel ? g_fIn : g_fTn;
        const float* inv = sel ? g_invI : g_invT;
#pragma unroll
        for (int r = 0; r < 4; r++) {
            int c = c0 + ty + r * 8;
            tile[ty + r * 8][tx] = src[(n * C + c) * P + p0 + tx] - g_mean[c];
        }
        __syncthreads();
#pragma unroll
        for (int r = 0; r < 4; r++) {
            int p = p0 + ty + r * 8;
            dst[(n * P + p) * C + c0 + tx] = tile[tx][ty + r * 8] * inv[n * P + p];
        }
        __syncthreads();
    }
}

// ---------------- 4) init stats ----------------------------------------------
__global__ void k_init() {
    int i = blockIdx.x * blockDim.x + threadIdx.x;
    if (i < NB * P) {
        g_colMin[i] = __float_as_int(3.0e38f);
        g_colSum[i] = 0.f;
    }
    if (i < NB) g_sampSum[i] = 0.f;
}

// ---------------- 5) per-sample GEMM: D = A * B^T, fused raw + colmin --------
// A = g_fTn[n] (M=P x K=C row-major), B = g_fIn[n] (N=P x K=C row-major)
// raw[p][j] = (1 - dot)/2, stored to g_D; column min via atomics.
__global__ __launch_bounds__(256, 2) void k_gemm() {
    const int n  = blockIdx.z;
    const int m0 = blockIdx.y * 128;
    const int j0 = blockIdx.x * 128;
    const float* A = g_fTn + n * P * C;
    const float* B = g_fIn + n * P * C;
    float*       D = g_D   + n * P * P;

    __shared__ float As[8][128];
    __shared__ float Bs[8][128];

    const int tid  = threadIdx.x;
    const int tm   = tid >> 4;          // 0..15
    const int tn   = tid & 15;          // 0..15
    const int lrow = tid >> 1;          // 0..127
    const int lk   = (tid & 1) * 4;     // 0 or 4

    float acc[8][8];
#pragma unroll
    for (int i = 0; i < 8; i++)
#pragma unroll
        for (int j = 0; j < 8; j++) acc[i][j] = 0.f;

    for (int k0 = 0; k0 < C; k0 += 8) {
        float4 av = *(const float4*)(A + (m0 + lrow) * C + k0 + lk);
        float4 bv = *(const float4*)(B + (j0 + lrow) * C + k0 + lk);
        As[lk + 0][lrow] = av.x; As[lk + 1][lrow] = av.y;
        As[lk + 2][lrow] = av.z; As[lk + 3][lrow] = av.w;
        Bs[lk + 0][lrow] = bv.x; Bs[lk + 1][lrow] = bv.y;
        Bs[lk + 2][lrow] = bv.z; Bs[lk + 3][lrow] = bv.w;
        __syncthreads();
#pragma unroll
        for (int k = 0; k < 8; k++) {
            float4 a0 = *(const float4*)&As[k][tm * 8];
            float4 a1 = *(const float4*)&As[k][tm * 8 + 4];
            float4 b0 = *(const float4*)&Bs[k][tn * 8];
            float4 b1 = *(const float4*)&Bs[k][tn * 8 + 4];
            float a[8] = {a0.x, a0.y, a0.z, a0.w, a1.x, a1.y, a1.z, a1.w};
            float b[8] = {b0.x, b0.y, b0.z, b0.w, b1.x, b1.y, b1.z, b1.w};
#pragma unroll
            for (int i = 0; i < 8; i++)
#pragma unroll
                for (int j = 0; j < 8; j++) acc[i][j] += a[i] * b[j];
        }
        __syncthreads();
    }

    // epilogue: raw = 0.5 - 0.5*dot ; store + column-min reduction
    __shared__ int cmin[128];
    if (tid < 128) cmin[tid] = __float_as_int(3.0e38f);
    __syncthreads();

#pragma unroll
    for (int i = 0; i < 8; i++) {
        int row = m0 + tm * 8 + i;
        float r0 = 0.5f - 0.5f * acc[i][0];
        float r1 = 0.5f - 0.5f * acc[i][1];
        float r2 = 0.5f - 0.5f * acc[i][2];
        float r3 = 0.5f - 0.5f * acc[i][3];
        float r4 = 0.5f - 0.5f * acc[i][4];
        float r5 = 0.5f - 0.5f * acc[i][5];
        float r6 = 0.5f - 0.5f * acc[i][6];
        float r7 = 0.5f - 0.5f * acc[i][7];
        float* dp = D + row * P + j0 + tn * 8;
        *(float4*)(dp)     = make_float4(r0, r1, r2, r3);
        *(float4*)(dp + 4) = make_float4(r4, r5, r6, r7);
    }
#pragma unroll
    for (int j = 0; j < 8; j++) {
        float mn = 3.0e38f;
#pragma unroll
        for (int i = 0; i < 8; i++) mn = fminf(mn, 0.5f - 0.5f * acc[i][j]);
        atomicMin(&cmin[tn * 8 + j], __float_as_int(mn));
    }
    __syncthreads();
    if (tid < 128) atomicMin(&g_colMin[n * P + j0 + tid], cmin[tid]);
}

// ---------------- 6) column exp-sum (partial rows per block) -----------------
#define ROWS_PER_BLK 144   // P / 16
__global__ void k_colsum() {
    int n = blockIdx.z;
    int j = blockIdx.x * 256 + threadIdx.x;
    int p0 = blockIdx.y * ROWS_PER_BLK;
    float m    = __int_as_float(g_colMin[n * P + j]);
    float binv = 1.0f / (SIGMA * (m + EPS));       // = 10/(m+eps)
    const float* base = g_D + n * P * P + j;
    float s = 0.f;
#pragma unroll 4
    for (int p = p0; p < p0 + ROWS_PER_BLK; p++) {
        float r = base[p * P];
        s += expf(INV_SIGMA - r * binv);
    }
    atomicAdd(&g_colSum[n * P + j], s);
}

// ---------------- 7) per-column constants b, c --------------------------------
__global__ void k_bc() {
    int i = blockIdx.x * blockDim.x + threadIdx.x;
    if (i >= NB * P) return;
    float m = __int_as_float(g_colMin[i]);
    g_bArr[i] = 1.0f / (SIGMA * (m + EPS));
    g_cArr[i] = INV_SIGMA - logf(g_colSum[i]);
}

// ---------------- 8) row max of (c_j - r*b_j), exp, per-sample sum ------------
__global__ void k_rowmax() {
    int R    = blockIdx.x * 8 + (threadIdx.x >> 5);   // global row id
    int lane = threadIdx.x & 31;
    int n = R / P, p = R - n * P;
    const float* row = g_D + n * P * P + p * P;
    const float* bA  = g_bArr + n * P;
    const float* cA  = g_cArr + n * P;
    float m = -3.0e38f;
#pragma unroll 4
    for (int j = lane; j < P; j += 32)
        m = fmaxf(m, cA[j] - row[j] * bA[j]);
#pragma unroll
    for (int o = 16; o; o >>= 1)
        m = fmaxf(m, __shfl_xor_sync(0xffffffffu, m, o));
    if (lane == 0) atomicAdd(&g_sampSum[n], expf(m));
}

// ---------------- 9) final outputs --------------------------------------------
__global__ void k_final(float* __restrict__ out, int out_size) {
    float cxb[NB];
    float loss = 0.f;
#pragma unroll
    for (int n = 0; n < NB; n++) {
        cxb[n] = -logf(g_sampSum[n] * (1.0f / P));
        loss += cxb[n];
    }
    loss *= (1.0f / NB);
    if (out_size >= 1 + NB) {
        out[0] = loss;
        for (int n = 0; n < NB; n++) out[1 + n] = cxb[n];
        for (int i = 1 + NB; i < out_size; i++) out[i] = 0.f;
    } else if (out_size == NB) {
        for (int n = 0; n < NB; n++) out[n] = cxb[n];
    } else if (out_size >= 1) {
        out[0] = loss;
    }
}

// ---------------- launch --------------------------------------------------------
extern "C" void kernel_launch(void* const* d_in, const int* in_sizes, int n_in,
                              void* d_out, int out_size) {
    const float* fT = (const float*)d_in[0];
    const float* fI = (const float*)d_in[1];
    float* out = (float*)d_out;

    k_mean<<<C, 256>>>(fT);
    k_inv<<<(NB * P) / 128, 128>>>(fT, fI);
    k_norm_transpose<<<dim3(P / 32, C / 32, NB), dim3(32, 8)>>>(fT, fI);
    k_init<<<(NB * P + 255) / 256, 256>>>();
    k_gemm<<<dim3(P / 128, P / 128, NB), 256>>>();
    k_colsum<<<dim3(P / 256, P / ROWS_PER_BLK, NB), 256>>>();
    k_bc<<<(NB * P + 255) / 256, 256>>>();
    k_rowmax<<<(NB * P) / 8, 256>>>();
    k_final<<<1, 1>>>(out, out_size);
}

// round 6
// speedup vs baseline: 3.1509x; 3.1509x over previous
#include <cuda_runtime.h>
#include <cuda_bf16.h>
#include <math.h>
#include <stdint.h>

#define NB 4
#define C 256
#define P 2304          // 48*48
#define SIGMA 0.1f
#define INV_SIGMA 10.0f
#define EPS 1e-5f

#define KTOT 768        // 3 x 256: A=[hi|hi|lo], B=[hi|lo|hi]
#define KC   64         // K per smem stage (128 bytes/row)
#define NK   (KTOT / KC)  // 12
#define STAGES 3
#define STG_BYTES 32768   // 16KB A + 16KB B
#define SMEM_TOT (STAGES * STG_BYTES)

// ---------------- scratch ----------------
__device__ float g_mean[C];
__device__ __align__(16) __nv_bfloat16 g_Abf[(size_t)NB * P * KTOT];
__device__ __align__(16) __nv_bfloat16 g_Bbf[(size_t)NB * P * KTOT];
__device__ float g_D[(size_t)NB * P * P];
__device__ int   g_colMin[NB * P];
__device__ float g_colSum[NB * P];
__device__ float g_bArr[NB * P];
__device__ float g_cArr[NB * P];
__device__ float g_sampSum[NB];

// ---------------- helpers ----------------
__device__ __forceinline__ uint32_t s2u(const void* p) {
    uint32_t a;
    asm("{ .reg .u64 t; cvta.to.shared.u64 t, %1; cvt.u32.u64 %0, t; }" : "=r"(a) : "l"(p));
    return a;
}
__device__ __forceinline__ void cp16(uint32_t s, const void* g) {
    asm volatile("cp.async.cg.shared.global [%0], [%1], 16;" :: "r"(s), "l"(g));
}
#define CP_COMMIT() asm volatile("cp.async.commit_group;" ::: "memory")
#define CP_WAIT1()  asm volatile("cp.async.wait_group 1;" ::: "memory")

#define LDSM4(d, addr)                                                          \
    asm volatile("ldmatrix.sync.aligned.m8n8.x4.shared.b16 {%0,%1,%2,%3}, [%4];" \
        : "=r"((d)[0]), "=r"((d)[1]), "=r"((d)[2]), "=r"((d)[3]) : "r"(addr))

#define MMA16816(c, a, b0, b1)                                                  \
    asm volatile("mma.sync.aligned.m16n8k16.row.col.f32.bf16.bf16.f32 "          \
        "{%0,%1,%2,%3}, {%4,%5,%6,%7}, {%8,%9}, {%0,%1,%2,%3};"                  \
        : "+f"((c)[0]), "+f"((c)[1]), "+f"((c)[2]), "+f"((c)[3])                 \
        : "r"((a)[0]), "r"((a)[1]), "r"((a)[2]), "r"((a)[3]), "r"(b0), "r"(b1))

// ---------------- 1) per-channel mean ----------------
__global__ void k_mean(const float* __restrict__ fT) {
    int c = blockIdx.x;
    float s = 0.f;
    for (int i = threadIdx.x; i < NB * P; i += blockDim.x) {
        int n = i / P, p = i - n * P;
        s += fT[((size_t)n * C + c) * P + p];
    }
    __shared__ float red[256];
    red[threadIdx.x] = s;
    __syncthreads();
    for (int o = 128; o > 0; o >>= 1) {
        if (threadIdx.x < o) red[threadIdx.x] += red[threadIdx.x + o];
        __syncthreads();
    }
    if (threadIdx.x == 0) g_mean[c] = red[0] * (1.0f / (NB * P));
}

// ---------------- 2) center + normalize + bf16 split pack ----------------
__global__ __launch_bounds__(256) void k_prep(const float* __restrict__ fT,
                                              const float* __restrict__ fI) {
    __shared__ float sT[C][17];
    __shared__ float sI[C][17];
    __shared__ float sm[C];
    __shared__ float part[2][256];
    __shared__ float invT[16], invI[16];
    int n = blockIdx.y, p0 = blockIdx.x * 16, tid = threadIdx.x;
    for (int c = tid; c < C; c += 256) sm[c] = g_mean[c];
    __syncthreads();
#pragma unroll
    for (int i = 0; i < 16; i++) {
        int idx = tid + i * 256;
        int c = idx >> 4, p = idx & 15;
        float m = sm[c];
        sT[c][p] = fT[((size_t)n * C + c) * P + p0 + p] - m;
        sI[c][p] = fI[((size_t)n * C + c) * P + p0 + p] - m;
    }
    __syncthreads();
    {
        int p = tid & 15, seg = tid >> 4;
        float aT = 0.f, aI = 0.f;
#pragma unroll
        for (int k = 0; k < 16; k++) {
            float x = sT[seg * 16 + k][p]; aT += x * x;
            float y = sI[seg * 16 + k][p]; aI += y * y;
        }
        part[0][tid] = aT;
        part[1][tid] = aI;
    }
    __syncthreads();
    if (tid < 16) {
        float aT = 0.f, aI = 0.f;
#pragma unroll
        for (int s = 0; s < 16; s++) { aT += part[0][s * 16 + tid]; aI += part[1][s * 16 + tid]; }
        invT[tid] = rsqrtf(aT);
        invI[tid] = rsqrtf(aI);
    }
    __syncthreads();
#pragma unroll 4
    for (int p = 0; p < 16; p++) {
        float vT = sT[tid][p] * invT[p];
        float vI = sI[tid][p] * invI[p];
        __nv_bfloat16 hT = __float2bfloat16(vT);
        __nv_bfloat16 lT = __float2bfloat16(vT - __bfloat162float(hT));
        __nv_bfloat16 hI = __float2bfloat16(vI);
        __nv_bfloat16 lI = __float2bfloat16(vI - __bfloat162float(hI));
        size_t base = ((size_t)n * P + p0 + p) * KTOT;
        g_Abf[base + tid]       = hT;
        g_Abf[base + 256 + tid] = hT;
        g_Abf[base + 512 + tid] = lT;
        g_Bbf[base + tid]       = hI;
        g_Bbf[base + 256 + tid] = lI;
        g_Bbf[base + 512 + tid] = hI;
    }
}

// ---------------- 3) init stats ----------------
__global__ void k_init() {
    int i = blockIdx.x * blockDim.x + threadIdx.x;
    if (i < NB * P) {
        g_colMin[i] = __float_as_int(3.0e38f);
        g_colSum[i] = 0.f;
    }
    if (i < NB) g_sampSum[i] = 0.f;
}

// ---------------- 4) bf16 mma.sync GEMM: D = 0.5 - 0.5*A''B''^T + col-min ----
// 128x128 block tile, 8 warps as 4(m) x 2(n) -> 32x64 warp tiles. 3-stage cp.async.
__global__ __launch_bounds__(256, 2) void k_gemm() {
    extern __shared__ __align__(128) char smem[];
    const int tid = threadIdx.x;
    const int n  = blockIdx.z;
    const int m0 = blockIdx.y * 128;
    const int j0 = blockIdx.x * 128;
    const uint32_t sb = s2u(smem);

    const char* Ab = (const char*)g_Abf + ((size_t)n * P + m0) * (KTOT * 2);
    const char* Bb = (const char*)g_Bbf + ((size_t)n * P + j0) * (KTOT * 2);

    const int lrow = tid >> 3;       // 0..31 (row step 32 per i-iter... see below)
    const int lcol = tid & 7;        // granule 0..7
    // load one stage: A,B each 128 rows x 8 granules(16B), 256 threads x 4 iters
    auto load_stage = [&](int ck, int s) {
        uint32_t sA = sb + s * STG_BYTES;
        uint32_t sB = sA + 16384;
        const char* As = Ab + ck * 128;
        const char* Bs = Bb + ck * 128;
#pragma unroll
        for (int i = 0; i < 4; i++) {
            int r = lrow + i * 32;
            int off = (r << 7) + ((lcol ^ (r & 7)) << 4);
            const size_t gsrc = (size_t)r * (KTOT * 2) + lcol * 16;
            cp16(sA + off, As + gsrc);
            cp16(sB + off, Bs + gsrc);
        }
    };

    const int warp = tid >> 5, lane = tid & 31;
    const int wm = warp & 3, wn = warp >> 2;
    const int aRow0 = wm * 32 + (lane & 15);
    const int bRow0 = wn * 64 + (lane & 15);
    const int gsel0 = lane >> 4;

    float acc[2][8][4];
#pragma unroll
    for (int mi = 0; mi < 2; mi++)
#pragma unroll
        for (int nj = 0; nj < 8; nj++)
#pragma unroll
            for (int q = 0; q < 4; q++) acc[mi][nj][q] = 0.f;

    load_stage(0, 0); CP_COMMIT();
    load_stage(1, 1); CP_COMMIT();

    for (int ko = 0; ko < NK; ko++) {
        CP_WAIT1();
        __syncthreads();
        if (ko + 2 < NK) load_stage(ko + 2, (ko + 2) % STAGES);
        CP_COMMIT();

        uint32_t sA = sb + (ko % STAGES) * STG_BYTES;
        uint32_t sB = sA + 16384;
#pragma unroll
        for (int ks = 0; ks < 4; ks++) {
            int gsel = ks * 2 + gsel0;
            uint32_t a[2][4];
#pragma unroll
            for (int mi = 0; mi < 2; mi++) {
                int r = aRow0 + mi * 16;
                LDSM4(a[mi], sA + (r << 7) + (((gsel ^ (r & 7))) << 4));
            }
            uint32_t b[4][4];
#pragma unroll
            for (int bi = 0; bi < 4; bi++) {
                int r = bRow0 + bi * 16;
                LDSM4(b[bi], sB + (r << 7) + (((gsel ^ (r & 7))) << 4));
            }
#pragma unroll
            for (int mi = 0; mi < 2; mi++)
#pragma unroll
                for (int nj = 0; nj < 8; nj++)
                    MMA16816(acc[mi][nj], a[mi], b[nj >> 1][nj & 1], b[nj >> 1][(nj & 1) + 2]);
        }
        __syncthreads();
    }

    // epilogue: raw = 0.5 - 0.5*dot; store + fused column-min
    __shared__ int cmin[128];
    if (tid < 128) cmin[tid] = __float_as_int(3.0e38f);
    __syncthreads();

    const size_t Dbase = (size_t)n * P * P;
#pragma unroll
    for (int mi = 0; mi < 2; mi++) {
        int r0 = m0 + wm * 32 + mi * 16 + (lane >> 2);
#pragma unroll
        for (int nj = 0; nj < 8; nj++) {
            int lc = wn * 64 + nj * 8 + ((lane & 3) << 1);
            int col = j0 + lc;
            float f0 = 0.5f - 0.5f * acc[mi][nj][0];
            float f1 = 0.5f - 0.5f * acc[mi][nj][1];
            float f2 = 0.5f - 0.5f * acc[mi][nj][2];
            float f3 = 0.5f - 0.5f * acc[mi][nj][3];
            *(float2*)&g_D[Dbase + (size_t)r0 * P + col]       = make_float2(f0, f1);
            *(float2*)&g_D[Dbase + (size_t)(r0 + 8) * P + col] = make_float2(f2, f3);
            atomicMin(&cmin[lc],     __float_as_int(fminf(f0, f2)));
            atomicMin(&cmin[lc + 1], __float_as_int(fminf(f1, f3)));
        }
    }
    __syncthreads();
    if (tid < 128) atomicMin(&g_colMin[n * P + j0 + tid], cmin[tid]);
}

// ---------------- 5) column exp-sum ----------------
#define ROWS_PER_BLK 144
__global__ void k_colsum() {
    int n = blockIdx.z;
    int j = blockIdx.x * 256 + threadIdx.x;
    int p0 = blockIdx.y * ROWS_PER_BLK;
    float m = __int_as_float(g_colMin[n * P + j]);
    float binv = 1.0f / (SIGMA * (m + EPS));
    const float* base = g_D + (size_t)n * P * P + j;
    float s = 0.f;
#pragma unroll 4
    for (int p = p0; p < p0 + ROWS_PER_BLK; p++) {
        float r = base[(size_t)p * P];
        s += __expf(INV_SIGMA - r * binv);
    }
    atomicAdd(&g_colSum[n * P + j], s);
}

// ---------------- 6) per-column constants ----------------
__global__ void k_bc() {
    int i = blockIdx.x * blockDim.x + threadIdx.x;
    if (i >= NB * P) return;
    float m = __int_as_float(g_colMin[i]);
    g_bArr[i] = 1.0f / (SIGMA * (m + EPS));
    g_cArr[i] = INV_SIGMA - logf(g_colSum[i]);
}

// ---------------- 7) row max -> exp -> per-sample sum ----------------
__global__ void k_rowmax() {
    int R = blockIdx.x * 8 + (threadIdx.x >> 5);
    int lane = threadIdx.x & 31;
    int n = R / P, p = R - n * P;
    const float* row = g_D + (size_t)n * P * P + (size_t)p * P;
    const float* bA = g_bArr + n * P;
    const float* cA = g_cArr + n * P;
    float m = -3.0e38f;
#pragma unroll 4
    for (int j = lane; j < P; j += 32)
        m = fmaxf(m, cA[j] - row[j] * bA[j]);
#pragma unroll
    for (int o = 16; o; o >>= 1)
        m = fmaxf(m, __shfl_xor_sync(0xffffffffu, m, o));
    if (lane == 0) atomicAdd(&g_sampSum[n], expf(m));
}

// ---------------- 8) final ----------------
__global__ void k_final(float* __restrict__ out, int out_size) {
    float cxb[NB];
    float loss = 0.f;
#pragma unroll
    for (int n = 0; n < NB; n++) {
        cxb[n] = -logf(g_sampSum[n] * (1.0f / P));
        loss += cxb[n];
    }
    loss *= (1.0f / NB);
    if (out_size >= 1 + NB) {
        out[0] = loss;
        for (int n = 0; n < NB; n++) out[1 + n] = cxb[n];
        for (int i = 1 + NB; i < out_size; i++) out[i] = 0.f;
    } else if (out_size == NB) {
        for (int n = 0; n < NB; n++) out[n] = cxb[n];
    } else if (out_size >= 1) {
        out[0] = loss;
    }
}

// ---------------- launch ----------------
extern "C" void kernel_launch(void* const* d_in, const int* in_sizes, int n_in,
                              void* d_out, int out_size) {
    const float* fT = (const float*)d_in[0];
    const float* fI = (const float*)d_in[1];
    float* out = (float*)d_out;

    cudaFuncSetAttribute(k_gemm, cudaFuncAttributeMaxDynamicSharedMemorySize, SMEM_TOT);

    k_mean<<<C, 256>>>(fT);
    k_prep<<<dim3(P / 16, NB), 256>>>(fT, fI);
    k_init<<<(NB * P + 255) / 256, 256>>>();
    k_gemm<<<dim3(P / 128, P / 128, NB), 256, SMEM_TOT>>>();
    k_colsum<<<dim3(P / 256, P / ROWS_PER_BLK, NB), 256>>>();
    k_bc<<<(NB * P + 255) / 256, 256>>>();
    k_rowmax<<<(NB * P) / 8, 256>>>();
    k_final<<<1, 1>>>(out, out_size);
}